// round 1
// baseline (speedup 1.0000x reference)
#include <cuda_runtime.h>
#include <math.h>

// Problem constants
#define NTOK 8192      // B*S
#define DK   2048      // hidden dim
#define NV   32000     // vocab
#define BM   64
#define BN   128
#define BK   16
#define NVT  (NV / BN)     // 250 vocab tiles
#define NMT  (NTOK / BM)   // 128 token tiles
#define IGNORE_IDX (-100)

// Scratch (device globals -- no allocations allowed)
__device__ float g_pmax[(size_t)NTOK * NVT];
__device__ float g_psum[(size_t)NTOK * NVT];
__device__ float g_tlogit[NTOK];
__device__ int   g_tgt32[NTOK];
__device__ float g_nll[NTOK];
__device__ float g_msk[NTOK];

// ---------------------------------------------------------------------------
// Normalize targets: harness may hand us int64 or int32 depending on jax x64
// config. For a true int64 array, every odd 32-bit word is 0 or -1 (sign ext);
// for 4096+ random int32 targets in [0,32000) that's essentially impossible.
// Scans only the first NTOK 32-bit words (safe for both layouts).
// ---------------------------------------------------------------------------
__global__ void prep_targets(const int* __restrict__ traw) {
    __shared__ int s_is64;
    int tid = threadIdx.x;
    if (tid == 0) s_is64 = 1;
    __syncthreads();

    int bad = 0;
    for (int i = tid; i < NTOK / 2; i += blockDim.x) {
        int hi = traw[2 * i + 1];
        if (hi != 0 && hi != -1) bad = 1;
    }
    if (bad) atomicAnd(&s_is64, 0);
    __syncthreads();
    int is64 = s_is64;

    for (int i = tid; i < NTOK; i += blockDim.x) {
        g_tgt32[i] = is64 ? traw[2 * i] : traw[i];
    }
}

// ---------------------------------------------------------------------------
// Fused GEMM + per-tile logsumexp partials.
// logits[m, n] = dot(H[m, :], W[n, :])   (H: [NTOK, DK], W: [NV, DK])
// Each block: BM x BN tile. Thread layout: ty=tid/32 owns 8 rows,
// tx=tid%32 owns 4 contiguous cols -> one warp covers 8 full rows of BN=128,
// so row-wise max/sumexp are clean warp shuffles.
// ---------------------------------------------------------------------------
__global__ void __launch_bounds__(256)
gemm_lse(const float* __restrict__ H, const float* __restrict__ W) {
    const int mt = blockIdx.x;          // token tile (fast dim: keeps H in L2)
    const int vt = blockIdx.y;          // vocab tile
    const int m0 = mt * BM;
    const int n0 = vt * BN;

    __shared__ float As[BK][BM];
    __shared__ float Bs[BK][BN];

    const int tid = threadIdx.x;
    const int tx = tid & 31;
    const int ty = tid >> 5;

    float acc[8][4];
#pragma unroll
    for (int i = 0; i < 8; i++)
#pragma unroll
        for (int j = 0; j < 4; j++) acc[i][j] = 0.0f;

    // A tile loader: 64 rows x 16 k -> one float4 per thread
    const int arow = tid >> 2;            // 0..63
    const int akc  = (tid & 3) * 4;       // 0,4,8,12
    const float* Hp = H + (size_t)(m0 + arow) * DK + akc;

    // B tile loader: 128 rows x 16 k -> two float4 per thread
    const int brow0 = tid >> 1;                 // 0..127
    const int bk0   = (tid & 1) * 8;            // 0 or 8
    const float* Wp0 = W + (size_t)(n0 + brow0) * DK + bk0;

    for (int k0 = 0; k0 < DK; k0 += BK) {
        float4 av  = *(const float4*)(Hp + k0);
        float4 bv0 = *(const float4*)(Wp0 + k0);
        float4 bv1 = *(const float4*)(Wp0 + k0 + 4);

        __syncthreads();   // previous iteration's reads done before overwrite
        As[akc + 0][arow] = av.x;
        As[akc + 1][arow] = av.y;
        As[akc + 2][arow] = av.z;
        As[akc + 3][arow] = av.w;
        Bs[bk0 + 0][brow0] = bv0.x;
        Bs[bk0 + 1][brow0] = bv0.y;
        Bs[bk0 + 2][brow0] = bv0.z;
        Bs[bk0 + 3][brow0] = bv0.w;
        Bs[bk0 + 4][brow0] = bv1.x;
        Bs[bk0 + 5][brow0] = bv1.y;
        Bs[bk0 + 6][brow0] = bv1.z;
        Bs[bk0 + 7][brow0] = bv1.w;
        __syncthreads();

#pragma unroll
        for (int kk = 0; kk < BK; kk++) {
            float a[8], b[4];
#pragma unroll
            for (int i = 0; i < 8; i++) a[i] = As[kk][ty * 8 + i];
#pragma unroll
            for (int j = 0; j < 4; j++) b[j] = Bs[kk][tx * 4 + j];
#pragma unroll
            for (int i = 0; i < 8; i++)
#pragma unroll
                for (int j = 0; j < 4; j++)
                    acc[i][j] = fmaf(a[i], b[j], acc[i][j]);
        }
    }

    // Epilogue: per-row max / sumexp over this BN-wide tile + target capture
#pragma unroll
    for (int i = 0; i < 8; i++) {
        const int m = m0 + ty * 8 + i;

        float mx = fmaxf(fmaxf(acc[i][0], acc[i][1]), fmaxf(acc[i][2], acc[i][3]));
#pragma unroll
        for (int off = 16; off; off >>= 1)
            mx = fmaxf(mx, __shfl_xor_sync(0xffffffffu, mx, off));

        float s = 0.0f;
#pragma unroll
        for (int j = 0; j < 4; j++) s += expf(acc[i][j] - mx);
#pragma unroll
        for (int off = 16; off; off >>= 1)
            s += __shfl_xor_sync(0xffffffffu, s, off);

        if (tx == 0) {
            g_pmax[(size_t)m * NVT + vt] = mx;
            g_psum[(size_t)m * NVT + vt] = s;
        }

        const int t = g_tgt32[m];
        const int c = t - n0;
        if (c >= 0 && c < BN && (c >> 2) == tx)
            g_tlogit[m] = acc[i][c & 3];
    }
}

// ---------------------------------------------------------------------------
// Combine per-tile partials into per-token NLL (one warp per token).
// ---------------------------------------------------------------------------
__global__ void combine_lse() {
    const int warp = (blockIdx.x * blockDim.x + threadIdx.x) >> 5;
    const int lane = threadIdx.x & 31;
    if (warp >= NTOK) return;

    float M = -INFINITY, S = 0.0f;
    for (int i = lane; i < NVT; i += 32) {
        float mi = g_pmax[(size_t)warp * NVT + i];
        float si = g_psum[(size_t)warp * NVT + i];
        if (mi > M) { S = S * expf(M - mi) + si; M = mi; }
        else        { S += si * expf(mi - M); }
    }
#pragma unroll
    for (int off = 16; off; off >>= 1) {
        float Mo = __shfl_xor_sync(0xffffffffu, M, off);
        float So = __shfl_xor_sync(0xffffffffu, S, off);
        if (Mo > M) { S = S * expf(M - Mo) + So; M = Mo; }
        else        { S += So * expf(Mo - M); }
    }

    if (lane == 0) {
        const int t = g_tgt32[warp];
        if (t == IGNORE_IDX) {
            g_nll[warp] = 0.0f;
            g_msk[warp] = 0.0f;
        } else {
            g_nll[warp] = (M + logf(S)) - g_tlogit[warp];
            g_msk[warp] = 1.0f;
        }
    }
}

// ---------------------------------------------------------------------------
// Deterministic final reduction (single block tree reduce; no float atomics).
// ---------------------------------------------------------------------------
__global__ void finalize(float* __restrict__ out) {
    __shared__ float ss[256];
    __shared__ float sc[256];
    const int tid = threadIdx.x;
    float s = 0.0f, c = 0.0f;
    for (int i = tid; i < NTOK; i += 256) {
        s += g_nll[i];
        c += g_msk[i];
    }
    ss[tid] = s;
    sc[tid] = c;
    __syncthreads();
    for (int o = 128; o; o >>= 1) {
        if (tid < o) { ss[tid] += ss[tid + o]; sc[tid] += sc[tid + o]; }
        __syncthreads();
    }
    if (tid == 0) out[0] = ss[0] / sc[0];
}

// ---------------------------------------------------------------------------
extern "C" void kernel_launch(void* const* d_in, const int* in_sizes, int n_in,
                              void* d_out, int out_size) {
    (void)in_sizes; (void)n_in; (void)out_size;
    const float* H    = (const float*)d_in[0];   // hidden [B,S,D] fp32
    const int*   traw = (const int*)d_in[1];     // targets (int64 or int32)
    const float* W    = (const float*)d_in[2];   // W [V,D] fp32
    float* out = (float*)d_out;

    prep_targets<<<1, 1024>>>(traw);

    dim3 grid(NMT, NVT);
    gemm_lse<<<grid, 256>>>(H, W);

    combine_lse<<<NTOK / 8, 256>>>();   // 8 warps (tokens) per 256-thread block

    finalize<<<1, 256>>>(out);
}

// round 3
// speedup vs baseline: 11.4406x; 11.4406x over previous
#include <cuda_runtime.h>
#include <cuda_bf16.h>
#include <math.h>
#include <stdint.h>

// Problem constants
#define NTOK 8192      // B*S
#define DK   2048      // hidden dim
#define NV   32000     // vocab
#define IGNORE_IDX (-100)

// GEMM tiling (mma.sync m16n8k16 bf16 path; sm_103 non-'a' target safe)
#define BM 128
#define BN 128
#define BK 32
#define NSTG 64        // DK / BK
#define NMT (NTOK / BM)    // 64
#define NVT128 (NV / BN)   // 250
#define NVT 1000           // 32-col logsumexp tiles per row (NV/32)

#define SLOT_BYTES 16384   // A 8KB + B 8KB
#define NSLOTS 3

// ------------------------- device scratch (static) -------------------------
__device__ __nv_bfloat16 g_Hb[(size_t)NTOK * DK];     // 32 MB
__device__ __nv_bfloat16 g_Wb[(size_t)NV * DK];       // 125 MB
__device__ float g_pmax[(size_t)NTOK * NVT];          // 32.8 MB
__device__ float g_psum[(size_t)NTOK * NVT];          // 32.8 MB
__device__ float g_tlogit[NTOK];
__device__ int   g_tgt32[NTOK];
__device__ float g_nll[NTOK];
__device__ float g_msk[NTOK];

// ------------------------------ PTX helpers --------------------------------
__device__ __forceinline__ uint32_t smem_u32(const void* p) {
    uint32_t a;
    asm("{ .reg .u64 t; cvta.to.shared.u64 t, %1; cvt.u32.u64 %0, t; }"
        : "=r"(a) : "l"(p));
    return a;
}

#define CP_ASYNC16(dst, src) \
    asm volatile("cp.async.cg.shared.global [%0], [%1], 16;" :: "r"(dst), "l"(src) : "memory")
#define CP_COMMIT() asm volatile("cp.async.commit_group;" ::: "memory")
#define CP_WAIT1()  asm volatile("cp.async.wait_group 1;" ::: "memory")
#define CP_WAIT0()  asm volatile("cp.async.wait_group 0;" ::: "memory")

#define LDMATRIX_X4(r0, r1, r2, r3, a) \
    asm volatile("ldmatrix.sync.aligned.m8n8.x4.shared.b16 {%0,%1,%2,%3}, [%4];" \
                 : "=r"(r0), "=r"(r1), "=r"(r2), "=r"(r3) : "r"(a))

#define MMA_BF16(d, a, b) \
    asm volatile("mma.sync.aligned.m16n8k16.row.col.f32.bf16.bf16.f32 " \
                 "{%0,%1,%2,%3}, {%4,%5,%6,%7}, {%8,%9}, {%0,%1,%2,%3};" \
                 : "+f"((d)[0]), "+f"((d)[1]), "+f"((d)[2]), "+f"((d)[3]) \
                 : "r"((a)[0]), "r"((a)[1]), "r"((a)[2]), "r"((a)[3]), \
                   "r"((b)[0]), "r"((b)[1]))

// swizzled 16B-chunk address within a 128-row x 64-byte tile
__device__ __forceinline__ uint32_t sw_addr(uint32_t base, int row, int chunk) {
    return base + (uint32_t)row * 64u + (uint32_t)((chunk ^ ((row >> 1) & 3)) * 16);
}

// --------------------------- target normalization ---------------------------
__global__ void prep_targets(const int* __restrict__ traw) {
    __shared__ int s_is64;
    int tid = threadIdx.x;
    if (tid == 0) s_is64 = 1;
    __syncthreads();
    int bad = 0;
    for (int i = tid; i < NTOK / 2; i += blockDim.x) {
        int hi = traw[2 * i + 1];
        if (hi != 0 && hi != -1) bad = 1;
    }
    if (bad) atomicAnd(&s_is64, 0);
    __syncthreads();
    int is64 = s_is64;
    for (int i = tid; i < NTOK; i += blockDim.x)
        g_tgt32[i] = is64 ? traw[2 * i] : traw[i];
}

// ------------------------------ fp32 -> bf16 --------------------------------
__global__ void conv_H(const float4* __restrict__ in, int n4) {
    int i = blockIdx.x * blockDim.x + threadIdx.x;
    if (i < n4) {
        float4 v = in[i];
        __nv_bfloat162 a = __float22bfloat162_rn(make_float2(v.x, v.y));
        __nv_bfloat162 b = __float22bfloat162_rn(make_float2(v.z, v.w));
        uint2 o; o.x = *(uint32_t*)&a; o.y = *(uint32_t*)&b;
        ((uint2*)g_Hb)[i] = o;
    }
}
__global__ void conv_W(const float4* __restrict__ in, int n4) {
    int i = blockIdx.x * blockDim.x + threadIdx.x;
    if (i < n4) {
        float4 v = in[i];
        __nv_bfloat162 a = __float22bfloat162_rn(make_float2(v.x, v.y));
        __nv_bfloat162 b = __float22bfloat162_rn(make_float2(v.z, v.w));
        uint2 o; o.x = *(uint32_t*)&a; o.y = *(uint32_t*)&b;
        ((uint2*)g_Wb)[i] = o;
    }
}

// ------------------------- GEMM + fused LSE epilogue -------------------------
__global__ void __launch_bounds__(256, 2)
gemm_lse() {
    extern __shared__ char dsm[];
    const uint32_t smem = smem_u32(dsm);

    const int tid = threadIdx.x;
    const int lane = tid & 31;
    const int w = tid >> 5;
    const int wm = w >> 2;        // 0..1  (64 rows each)
    const int wn = w & 3;         // 0..3  (32 cols each)

    const int m0 = blockIdx.x * BM;
    const int n0 = blockIdx.y * BN;

    const __nv_bfloat16* Ag = g_Hb + (size_t)m0 * DK;
    const __nv_bfloat16* Bg = g_Wb + (size_t)n0 * DK;

    // per-thread load assignment: 2 A-chunks + 2 B-chunks per stage
    const int id0 = tid, id1 = tid + 256;
    const int ar0 = id0 >> 2, ac0 = id0 & 3;
    const int ar1 = id1 >> 2, ac1 = id1 & 3;

    float acc[4][4][4];
#pragma unroll
    for (int i = 0; i < 4; i++)
#pragma unroll
        for (int j = 0; j < 4; j++)
#pragma unroll
            for (int k = 0; k < 4; k++) acc[i][j][k] = 0.0f;

    // ldmatrix lane addressing (precomputed)
    const int a_row_l = ((lane >> 3) & 1) * 8 + (lane & 7);
    const int a_coff  = lane >> 4;
    const int b_n_l   = ((lane >> 4) & 1) * 8 + (lane & 7);
    const int b_kc    = (lane >> 3) & 1;

#define LOAD_STAGE(st, slot)                                                    \
    do {                                                                        \
        uint32_t sA = smem + (uint32_t)(slot) * SLOT_BYTES;                     \
        uint32_t sB = sA + 8192u;                                               \
        const char* a0 = (const char*)(Ag + (size_t)ar0 * DK + (st) * BK + ac0 * 8); \
        const char* a1 = (const char*)(Ag + (size_t)ar1 * DK + (st) * BK + ac1 * 8); \
        const char* b0 = (const char*)(Bg + (size_t)ar0 * DK + (st) * BK + ac0 * 8); \
        const char* b1 = (const char*)(Bg + (size_t)ar1 * DK + (st) * BK + ac1 * 8); \
        CP_ASYNC16(sw_addr(sA, ar0, ac0), a0);                                  \
        CP_ASYNC16(sw_addr(sA, ar1, ac1), a1);                                  \
        CP_ASYNC16(sw_addr(sB, ar0, ac0), b0);                                  \
        CP_ASYNC16(sw_addr(sB, ar1, ac1), b1);                                  \
        CP_COMMIT();                                                            \
    } while (0)

    LOAD_STAGE(0, 0);
    LOAD_STAGE(1, 1);

    for (int st = 0; st < NSTG; st++) {
        if (st < NSTG - 2) CP_WAIT1(); else CP_WAIT0();
        __syncthreads();

        if (st + 2 < NSTG) LOAD_STAGE(st + 2, (st + 2) % NSLOTS);

        const uint32_t sA = smem + (uint32_t)(st % NSLOTS) * SLOT_BYTES;
        const uint32_t sB = sA + 8192u;

#pragma unroll
        for (int ks = 0; ks < 2; ks++) {
            uint32_t a[4][4];
#pragma unroll
            for (int mi = 0; mi < 4; mi++) {
                int r = wm * 64 + mi * 16 + a_row_l;
                int ch = ks * 2 + a_coff;
                LDMATRIX_X4(a[mi][0], a[mi][1], a[mi][2], a[mi][3],
                            sw_addr(sA, r, ch));
            }
            uint32_t b[4][2];
#pragma unroll
            for (int bi = 0; bi < 2; bi++) {
                int n = wn * 32 + bi * 16 + b_n_l;
                int ch = ks * 2 + b_kc;
                LDMATRIX_X4(b[2 * bi][0], b[2 * bi][1], b[2 * bi + 1][0], b[2 * bi + 1][1],
                            sw_addr(sB, n, ch));
            }
#pragma unroll
            for (int mi = 0; mi < 4; mi++)
#pragma unroll
                for (int ni = 0; ni < 4; ni++)
                    MMA_BF16(acc[mi][ni], a[mi], b[ni]);
        }
        __syncthreads();
    }

    // ---- fused epilogue: per-row (32-col tile) max + sumexp + target pick ----
    const int ntg = (n0 >> 5) + wn;      // global 32-col tile index
    const int cbase = n0 + wn * 32;

#pragma unroll
    for (int mi = 0; mi < 4; mi++) {
#pragma unroll
        for (int h = 0; h < 2; h++) {
            float v[8];
#pragma unroll
            for (int ni = 0; ni < 4; ni++) {
                v[ni * 2]     = acc[mi][ni][h * 2];
                v[ni * 2 + 1] = acc[mi][ni][h * 2 + 1];
            }
            float mx = v[0];
#pragma unroll
            for (int i = 1; i < 8; i++) mx = fmaxf(mx, v[i]);
            mx = fmaxf(mx, __shfl_xor_sync(0xffffffffu, mx, 1));
            mx = fmaxf(mx, __shfl_xor_sync(0xffffffffu, mx, 2));
            float s = 0.0f;
#pragma unroll
            for (int i = 0; i < 8; i++) s += __expf(v[i] - mx);
            s += __shfl_xor_sync(0xffffffffu, s, 1);
            s += __shfl_xor_sync(0xffffffffu, s, 2);

            const int r = wm * 64 + mi * 16 + h * 8 + (lane >> 2);
            const int m = m0 + r;
            if ((lane & 3) == 0) {
                g_pmax[(size_t)m * NVT + ntg] = mx;
                g_psum[(size_t)m * NVT + ntg] = s;
            }
            const int tg = g_tgt32[m];
            const int rel = tg - cbase - (lane & 3) * 2;
#pragma unroll
            for (int ni = 0; ni < 4; ni++) {
                if (rel == ni * 8)     g_tlogit[m] = v[ni * 2];
                if (rel == ni * 8 + 1) g_tlogit[m] = v[ni * 2 + 1];
            }
        }
    }
}

// ----------------------------- combine + final ------------------------------
__global__ void combine_lse() {
    const int warp = (blockIdx.x * blockDim.x + threadIdx.x) >> 5;
    const int lane = threadIdx.x & 31;
    if (warp >= NTOK) return;

    float M = -INFINITY, S = 0.0f;
    for (int i = lane; i < NVT; i += 32) {
        float mi = g_pmax[(size_t)warp * NVT + i];
        float si = g_psum[(size_t)warp * NVT + i];
        if (mi > M) { S = S * __expf(M - mi) + si; M = mi; }
        else        { S += si * __expf(mi - M); }
    }
#pragma unroll
    for (int off = 16; off; off >>= 1) {
        float Mo = __shfl_xor_sync(0xffffffffu, M, off);
        float So = __shfl_xor_sync(0xffffffffu, S, off);
        if (Mo > M) { S = S * __expf(M - Mo) + So; M = Mo; }
        else        { S += So * __expf(Mo - M); }
    }
    if (lane == 0) {
        const int t = g_tgt32[warp];
        if (t == IGNORE_IDX) { g_nll[warp] = 0.0f; g_msk[warp] = 0.0f; }
        else {
            g_nll[warp] = (M + logf(S)) - g_tlogit[warp];
            g_msk[warp] = 1.0f;
        }
    }
}

__global__ void finalize(float* __restrict__ out) {
    __shared__ float ss_[256];
    __shared__ float sc_[256];
    const int tid = threadIdx.x;
    float s = 0.0f, c = 0.0f;
    for (int i = tid; i < NTOK; i += 256) { s += g_nll[i]; c += g_msk[i]; }
    ss_[tid] = s; sc_[tid] = c;
    __syncthreads();
    for (int o = 128; o; o >>= 1) {
        if (tid < o) { ss_[tid] += ss_[tid + o]; sc_[tid] += sc_[tid + o]; }
        __syncthreads();
    }
    if (tid == 0) out[0] = ss_[0] / sc_[0];
}

// ---------------------------------------------------------------------------
extern "C" void kernel_launch(void* const* d_in, const int* in_sizes, int n_in,
                              void* d_out, int out_size) {
    (void)in_sizes; (void)n_in; (void)out_size;
    const float* H    = (const float*)d_in[0];
    const int*   traw = (const int*)d_in[1];
    const float* W    = (const float*)d_in[2];
    float* out = (float*)d_out;

    static bool attr_set = false;
    if (!attr_set) {
        cudaFuncSetAttribute(gemm_lse, cudaFuncAttributeMaxDynamicSharedMemorySize,
                             NSLOTS * SLOT_BYTES);
        attr_set = true;
    }

    prep_targets<<<1, 1024>>>(traw);

    {
        int n4h = NTOK * DK / 4;
        int n4w = NV * DK / 4;
        conv_H<<<n4h / 256, 256>>>((const float4*)H, n4h);
        conv_W<<<n4w / 256, 256>>>((const float4*)W, n4w);
    }

    dim3 grid(NMT, NVT128);
    gemm_lse<<<grid, 256, NSLOTS * SLOT_BYTES>>>();

    combine_lse<<<NTOK / 8, 256>>>();
    finalize<<<1, 256>>>(out);
}

// round 4
// speedup vs baseline: 12.8426x; 1.1225x over previous
#include <cuda_runtime.h>
#include <cuda_bf16.h>
#include <math.h>
#include <stdint.h>

// Problem constants
#define NTOK 8192      // B*S
#define DK   2048      // hidden dim
#define NV   32000     // vocab
#define IGNORE_IDX (-100)

// GEMM tiling: 128x128 CTA tile, 4 warps (2x2), warp tile 64x64
#define BM 128
#define BN 128
#define BK 32
#define NSTG (DK / BK)     // 64
#define NMT (NTOK / BM)    // 64
#define NVT128 (NV / BN)   // 250
#define NVT 1000           // 32-col logsumexp tiles per row (NV/32)

#define SLOT_BYTES 16384   // A 8KB + B 8KB
#define NSLOTS 4

// ------------------------- device scratch (static) -------------------------
__device__ __nv_bfloat16 g_Hb[(size_t)NTOK * DK];     // 32 MB
__device__ __nv_bfloat16 g_Wb[(size_t)NV * DK];       // 125 MB
__device__ float g_pmax[(size_t)NTOK * NVT];          // 32.8 MB
__device__ float g_psum[(size_t)NTOK * NVT];          // 32.8 MB
__device__ float g_tlogit[NTOK];
__device__ int   g_tgt32[NTOK];
__device__ float g_nll[NTOK];
__device__ float g_msk[NTOK];

// ------------------------------ PTX helpers --------------------------------
__device__ __forceinline__ uint32_t smem_u32(const void* p) {
    uint32_t a;
    asm("{ .reg .u64 t; cvta.to.shared.u64 t, %1; cvt.u32.u64 %0, t; }"
        : "=r"(a) : "l"(p));
    return a;
}

#define CP_ASYNC16(dst, src) \
    asm volatile("cp.async.cg.shared.global [%0], [%1], 16;" :: "r"(dst), "l"(src) : "memory")
#define CP_COMMIT() asm volatile("cp.async.commit_group;" ::: "memory")
#define CP_WAIT2()  asm volatile("cp.async.wait_group 2;" ::: "memory")
#define CP_WAIT0()  asm volatile("cp.async.wait_group 0;" ::: "memory")

#define LDMATRIX_X4(r0, r1, r2, r3, a) \
    asm volatile("ldmatrix.sync.aligned.m8n8.x4.shared.b16 {%0,%1,%2,%3}, [%4];" \
                 : "=r"(r0), "=r"(r1), "=r"(r2), "=r"(r3) : "r"(a))

#define MMA_BF16(d, a, b) \
    asm volatile("mma.sync.aligned.m16n8k16.row.col.f32.bf16.bf16.f32 " \
                 "{%0,%1,%2,%3}, {%4,%5,%6,%7}, {%8,%9}, {%0,%1,%2,%3};" \
                 : "+f"((d)[0]), "+f"((d)[1]), "+f"((d)[2]), "+f"((d)[3]) \
                 : "r"((a)[0]), "r"((a)[1]), "r"((a)[2]), "r"((a)[3]), \
                   "r"((b)[0]), "r"((b)[1]))

// swizzled 16B-chunk address within a 128-row x 64-byte tile
__device__ __forceinline__ uint32_t sw_addr(uint32_t base, int row, int chunk) {
    return base + (uint32_t)row * 64u + (uint32_t)((chunk ^ ((row >> 1) & 3)) * 16);
}

// --------------------------- target normalization ---------------------------
__global__ void prep_targets(const int* __restrict__ traw) {
    __shared__ int s_is64;
    int tid = threadIdx.x;
    if (tid == 0) s_is64 = 1;
    __syncthreads();
    int bad = 0;
    for (int i = tid; i < NTOK / 2; i += blockDim.x) {
        int hi = traw[2 * i + 1];
        if (hi != 0 && hi != -1) bad = 1;
    }
    if (bad) atomicAnd(&s_is64, 0);
    __syncthreads();
    int is64 = s_is64;
    for (int i = tid; i < NTOK; i += blockDim.x)
        g_tgt32[i] = is64 ? traw[2 * i] : traw[i];
}

// ------------------------------ fp32 -> bf16 --------------------------------
__global__ void conv_H(const float4* __restrict__ in, int n4) {
    int i = blockIdx.x * blockDim.x + threadIdx.x;
    if (i < n4) {
        float4 v = in[i];
        __nv_bfloat162 a = __float22bfloat162_rn(make_float2(v.x, v.y));
        __nv_bfloat162 b = __float22bfloat162_rn(make_float2(v.z, v.w));
        uint2 o; o.x = *(uint32_t*)&a; o.y = *(uint32_t*)&b;
        ((uint2*)g_Hb)[i] = o;
    }
}
__global__ void conv_W(const float4* __restrict__ in, int n4) {
    int i = blockIdx.x * blockDim.x + threadIdx.x;
    if (i < n4) {
        float4 v = in[i];
        __nv_bfloat162 a = __float22bfloat162_rn(make_float2(v.x, v.y));
        __nv_bfloat162 b = __float22bfloat162_rn(make_float2(v.z, v.w));
        uint2 o; o.x = *(uint32_t*)&a; o.y = *(uint32_t*)&b;
        ((uint2*)g_Wb)[i] = o;
    }
}

// ------------------------- GEMM + fused LSE epilogue -------------------------
__global__ void __launch_bounds__(128, 2)
gemm_lse() {
    extern __shared__ char dsm[];
    const uint32_t smem = smem_u32(dsm);

    const int tid = threadIdx.x;
    const int lane = tid & 31;
    const int w = tid >> 5;
    const int wm = w >> 1;        // 0..1 (64 rows each)
    const int wn = w & 1;         // 0..1 (64 cols each)

    const int m0 = blockIdx.x * BM;
    const int n0 = blockIdx.y * BN;

    const __nv_bfloat16* Ag = g_Hb + (size_t)m0 * DK;
    const __nv_bfloat16* Bg = g_Wb + (size_t)n0 * DK;

    // per-thread load assignment: 4 A-chunks + 4 B-chunks per stage
    // id = tid + 128*j, row = id>>2 (0..127), col = id&3
    int lrow[4], lcol[4];
#pragma unroll
    for (int j = 0; j < 4; j++) {
        int id = tid + 128 * j;
        lrow[j] = id >> 2;
        lcol[j] = id & 3;
    }

    float acc[4][8][4];
#pragma unroll
    for (int i = 0; i < 4; i++)
#pragma unroll
        for (int j = 0; j < 8; j++)
#pragma unroll
            for (int k = 0; k < 4; k++) acc[i][j][k] = 0.0f;

    // ldmatrix lane addressing (same fragment order as validated R3 kernel)
    const int a_row_l = ((lane >> 3) & 1) * 8 + (lane & 7);
    const int a_coff  = lane >> 4;
    const int b_n_l   = ((lane >> 4) & 1) * 8 + (lane & 7);
    const int b_kc    = (lane >> 3) & 1;

#define LOAD_STAGE(st, slot)                                                     \
    do {                                                                         \
        uint32_t sA = smem + (uint32_t)(slot) * SLOT_BYTES;                      \
        uint32_t sB = sA + 8192u;                                                \
        _Pragma("unroll")                                                        \
        for (int j = 0; j < 4; j++) {                                            \
            const char* as = (const char*)(Ag + (size_t)lrow[j] * DK + (st) * BK + lcol[j] * 8); \
            const char* bs = (const char*)(Bg + (size_t)lrow[j] * DK + (st) * BK + lcol[j] * 8); \
            CP_ASYNC16(sw_addr(sA, lrow[j], lcol[j]), as);                       \
            CP_ASYNC16(sw_addr(sB, lrow[j], lcol[j]), bs);                       \
        }                                                                        \
        CP_COMMIT();                                                             \
    } while (0)

    LOAD_STAGE(0, 0);
    LOAD_STAGE(1, 1);
    LOAD_STAGE(2, 2);

    for (int st = 0; st < NSTG; st++) {
        if (st < NSTG - 3) CP_WAIT2(); else CP_WAIT0();
        __syncthreads();   // also orders: prior iter's reads precede slot reuse below

        if (st + 3 < NSTG) LOAD_STAGE(st + 3, (st + 3) & 3);

        const uint32_t sA = smem + (uint32_t)(st & 3) * SLOT_BYTES;
        const uint32_t sB = sA + 8192u;

#pragma unroll
        for (int ks = 0; ks < 2; ks++) {
            uint32_t a[4][4];
#pragma unroll
            for (int mi = 0; mi < 4; mi++) {
                int r = wm * 64 + mi * 16 + a_row_l;
                int ch = ks * 2 + a_coff;
                LDMATRIX_X4(a[mi][0], a[mi][1], a[mi][2], a[mi][3],
                            sw_addr(sA, r, ch));
            }
            uint32_t b[8][2];
#pragma unroll
            for (int bi = 0; bi < 4; bi++) {
                int n = wn * 64 + bi * 16 + b_n_l;
                int ch = ks * 2 + b_kc;
                LDMATRIX_X4(b[2 * bi][0], b[2 * bi][1], b[2 * bi + 1][0], b[2 * bi + 1][1],
                            sw_addr(sB, n, ch));
            }
#pragma unroll
            for (int mi = 0; mi < 4; mi++)
#pragma unroll
                for (int ni = 0; ni < 8; ni++)
                    MMA_BF16(acc[mi][ni], a[mi], b[ni]);
        }
        // no trailing sync: next iter's leading sync orders reads vs. overwrite
    }

    // ---- fused epilogue: per-row 32-col-group max + sumexp + target pick ----
#pragma unroll
    for (int mi = 0; mi < 4; mi++) {
#pragma unroll
        for (int h = 0; h < 2; h++) {
            const int r = wm * 64 + mi * 16 + h * 8 + (lane >> 2);
            const int m = m0 + r;
            const int tg = g_tgt32[m];
#pragma unroll
            for (int g = 0; g < 2; g++) {
                float v[8];
#pragma unroll
                for (int nl = 0; nl < 4; nl++) {
                    v[nl * 2]     = acc[mi][g * 4 + nl][h * 2];
                    v[nl * 2 + 1] = acc[mi][g * 4 + nl][h * 2 + 1];
                }
                float mx = v[0];
#pragma unroll
                for (int i = 1; i < 8; i++) mx = fmaxf(mx, v[i]);
                mx = fmaxf(mx, __shfl_xor_sync(0xffffffffu, mx, 1));
                mx = fmaxf(mx, __shfl_xor_sync(0xffffffffu, mx, 2));
                float s = 0.0f;
#pragma unroll
                for (int i = 0; i < 8; i++) s += __expf(v[i] - mx);
                s += __shfl_xor_sync(0xffffffffu, s, 1);
                s += __shfl_xor_sync(0xffffffffu, s, 2);

                const int ntg = (n0 >> 5) + wn * 2 + g;
                if ((lane & 3) == 0) {
                    g_pmax[(size_t)m * NVT + ntg] = mx;
                    g_psum[(size_t)m * NVT + ntg] = s;
                }
                const int cbase = n0 + wn * 64 + g * 32;
                const int rel = tg - cbase - (lane & 3) * 2;
#pragma unroll
                for (int nl = 0; nl < 4; nl++) {
                    if (rel == nl * 8)     g_tlogit[m] = v[nl * 2];
                    if (rel == nl * 8 + 1) g_tlogit[m] = v[nl * 2 + 1];
                }
            }
        }
    }
}

// ----------------------------- combine + final ------------------------------
__global__ void combine_lse() {
    const int warp = (blockIdx.x * blockDim.x + threadIdx.x) >> 5;
    const int lane = threadIdx.x & 31;
    if (warp >= NTOK) return;

    float M = -INFINITY, S = 0.0f;
    for (int i = lane; i < NVT; i += 32) {
        float mi = g_pmax[(size_t)warp * NVT + i];
        float si = g_psum[(size_t)warp * NVT + i];
        if (mi > M) { S = S * __expf(M - mi) + si; M = mi; }
        else        { S += si * __expf(mi - M); }
    }
#pragma unroll
    for (int off = 16; off; off >>= 1) {
        float Mo = __shfl_xor_sync(0xffffffffu, M, off);
        float So = __shfl_xor_sync(0xffffffffu, S, off);
        if (Mo > M) { S = S * __expf(M - Mo) + So; M = Mo; }
        else        { S += So * __expf(Mo - M); }
    }
    if (lane == 0) {
        const int t = g_tgt32[warp];
        if (t == IGNORE_IDX) { g_nll[warp] = 0.0f; g_msk[warp] = 0.0f; }
        else {
            g_nll[warp] = (M + logf(S)) - g_tlogit[warp];
            g_msk[warp] = 1.0f;
        }
    }
}

__global__ void finalize(float* __restrict__ out) {
    __shared__ float ss_[256];
    __shared__ float sc_[256];
    const int tid = threadIdx.x;
    float s = 0.0f, c = 0.0f;
    for (int i = tid; i < NTOK; i += 256) { s += g_nll[i]; c += g_msk[i]; }
    ss_[tid] = s; sc_[tid] = c;
    __syncthreads();
    for (int o = 128; o; o >>= 1) {
        if (tid < o) { ss_[tid] += ss_[tid + o]; sc_[tid] += sc_[tid + o]; }
        __syncthreads();
    }
    if (tid == 0) out[0] = ss_[0] / sc_[0];
}

// ---------------------------------------------------------------------------
extern "C" void kernel_launch(void* const* d_in, const int* in_sizes, int n_in,
                              void* d_out, int out_size) {
    (void)in_sizes; (void)n_in; (void)out_size;
    const float* H    = (const float*)d_in[0];
    const int*   traw = (const int*)d_in[1];
    const float* W    = (const float*)d_in[2];
    float* out = (float*)d_out;

    static bool attr_set = false;
    if (!attr_set) {
        cudaFuncSetAttribute(gemm_lse, cudaFuncAttributeMaxDynamicSharedMemorySize,
                             NSLOTS * SLOT_BYTES);
        attr_set = true;
    }

    prep_targets<<<1, 1024>>>(traw);

    {
        int n4h = NTOK * DK / 4;
        int n4w = NV * DK / 4;
        conv_H<<<n4h / 256, 256>>>((const float4*)H, n4h);
        conv_W<<<n4w / 256, 256>>>((const float4*)W, n4w);
    }

    dim3 grid(NMT, NVT128);
    gemm_lse<<<grid, 128, NSLOTS * SLOT_BYTES>>>();

    combine_lse<<<NTOK / 8, 256>>>();
    finalize<<<1, 256>>>(out);
}